// round 7
// baseline (speedup 1.0000x reference)
#include <cuda_runtime.h>

#define MAXN 80000
#define KOBJ 512
#define FEPS 1e-9f
#define CGRID 296   // 2 blocks/SM on 148 SMs -> guaranteed single wave

// ---------------- scratch (static device globals; no allocation) ----------------
// Zero-initialized at module load; passC's last block re-zeros each run.
__device__ float4 g_hit[MAXN];                 // x, y, q, x^2+y^2+1e-6
__device__ unsigned long long g_key[KOBJ];     // packed (beta_bits<<32) | ~index
__device__ float g_cnt[KOBJ], g_num[KOBJ], g_den[KOBJ];
__device__ float g_att[KOBJ], g_rep[KOBJ];
__device__ float g_scal[4];                    // noise_beta_sum, noise_cnt, cc_sum
__device__ unsigned int g_done;                // block-completion counter

// ---------------- helpers ----------------
__device__ __forceinline__ float asqrtf(float x) {
    float r;
    asm("sqrt.approx.f32 %0, %1;" : "=f"(r) : "f"(x));
    return r;
}
__device__ __forceinline__ float softclipf(float v, float s) {
    float x = v / s;
    if (x > 1.0f) x = __logf(x + 1.0f);
    return x * s;
}
typedef unsigned long long ull;
__device__ __forceinline__ ull pk2(float lo, float hi) {
    ull r; asm("mov.b64 %0, {%1, %2};" : "=l"(r) : "f"(lo), "f"(hi)); return r;
}
__device__ __forceinline__ void upk2(float& lo, float& hi, ull v) {
    asm("mov.b64 {%0, %1}, %2;" : "=f"(lo), "=f"(hi) : "l"(v));
}
__device__ __forceinline__ ull fma2(ull a, ull b, ull c) {
    ull d; asm("fma.rn.f32x2 %0, %1, %2, %3;" : "=l"(d) : "l"(a), "l"(b), "l"(c)); return d;
}
__device__ __forceinline__ ull add2(ull a, ull b) {
    ull d; asm("add.rn.f32x2 %0, %1, %2;" : "=l"(d) : "l"(a), "l"(b)); return d;
}

// ---------------- kernel 1: per-hit precompute + per-object atomics ----------------
__global__ void passA_kernel(const float* __restrict__ pbeta, const float* __restrict__ pcc,
                             const float* __restrict__ pen,   const float* __restrict__ ppos,
                             const float* __restrict__ ptime, const float* __restrict__ pid,
                             const int*   __restrict__ tidx,  const float* __restrict__ ten,
                             const float* __restrict__ tpos,  const float* __restrict__ ttime,
                             int N)
{
    int i = blockIdx.x * blockDim.x + threadIdx.x;
    float ccs = 0.f, nb = 0.f, nc = 0.f;
    if (i < N) {
        // hoisted, independent loads -> one batched round trip
        float  bref = pbeta[i];
        float2 cc   = ((const float2*)pcc)[i];
        float  pe   = pen[i];
        float2 pp   = ((const float2*)ppos)[i];
        float  pt   = ptime[i];
        int    k    = tidx[i];
        float  tev  = ten[i];
        float2 tp   = ((const float2*)tpos)[i];
        float  tt   = ttime[i];
        const float2* pid2 = (const float2*)pid;
        float2 c0 = pid2[3 * i], c1 = pid2[3 * i + 1], c2v = pid2[3 * i + 2];

        float b = fminf(fmaxf(bref, 1e-6f), 1.0f - 1e-6f);
        float a = 0.5f * __logf(__fdividef(1.0f + b, 1.0f - b));   // atanh
        float q = a * a + 0.1f;
        ccs = cc.x * cc.x + cc.y * cc.y;
        g_hit[i] = make_float4(cc.x, cc.y, q, ccs + 1e-6f);

        float ed = fabsf(tev - pe);
        float el = softclipf(10.0f * __expf(-0.1f * ed * ed) + 0.01f * ed, 10.0f);
        float dx = tp.x - pp.x, dy = tp.y - pp.y;
        float d2 = dx * dx + dy * dy;
        float arg = asqrtf(d2 * 0.01f + 0.01f);
        float hub = (arg < 10.0f) ? arg * arg : 100.0f + 20.0f * (arg - 10.0f);
        float pl = softclipf(hub, 3.0f);
        float dt  = tt - pt;
        float adt = fabsf(dt);
        float th = (adt < 2.0f) ? dt * dt : 4.0f + 4.0f * (adt - 2.0f);
        float tl = softclipf(th, 6.0f);
        float cs = c0.x * c0.x + c0.y * c0.y + c1.x * c1.x + c1.y * c1.y
                 + c2v.x * c2v.x + c2v.y * c2v.y;
        float cl = 1e-8f * (cs * (1.0f / 6.0f));
        float payload = el + pl + tl + cl;
        float w  = (tev > 10.0f) ? 1.0f : fmaxf((tev - 0.5f) * (1.0f / 9.5f), 0.0f);
        float pw = b * w;

        if (k < 0) {
            nb = b; nc = 1.f;
        } else {
            atomicAdd(&g_cnt[k], 1.f);
            unsigned long long key =
                ((unsigned long long)__float_as_uint(b) << 32)
                | (unsigned long long)(0xFFFFFFFFu - (unsigned)i);
            atomicMax(&g_key[k], key);
            atomicAdd(&g_num[k], payload * pw);
            atomicAdd(&g_den[k], pw);
        }
    }
    #pragma unroll
    for (int o = 16; o; o >>= 1) {
        ccs += __shfl_down_sync(0xFFFFFFFFu, ccs, o);
        nb  += __shfl_down_sync(0xFFFFFFFFu, nb,  o);
        nc  += __shfl_down_sync(0xFFFFFFFFu, nc,  o);
    }
    if ((threadIdx.x & 31) == 0) {
        if (ccs != 0.f) atomicAdd(&g_scal[2], ccs);
        if (nc  != 0.f) { atomicAdd(&g_scal[0], nb); atomicAdd(&g_scal[1], nc); }
    }
}

// ---------------- kernel 2: fused N x K sweep + inline finalization ----------------
__global__ void __launch_bounds__(128) passC_kernel(const int* __restrict__ tidx, int N,
                                                    float* __restrict__ out) {
    int t = threadIdx.x;                       // thread owns k = t, t+128, t+256, t+384
    ull mx2[4], my2[4], c22[4];                // object constants broadcast-packed once
    #pragma unroll
    for (int j = 0; j < 4; j++) {
        int k = t + 128 * j;
        float mx = 0.f, my = 0.f, c2 = 0.f;
        if (__ldg(&g_cnt[k]) > 0.f) {
            unsigned a = 0xFFFFFFFFu - (unsigned)(__ldg(&g_key[k]) & 0xFFFFFFFFull);
            float4 h = __ldg(&g_hit[a]);
            mx = -2.f * h.x; my = -2.f * h.y; c2 = h.x * h.x + h.y * h.y;
        }
        mx2[j] = pk2(mx, mx); my2[j] = pk2(my, my); c22[j] = pk2(c2, c2);
    }
    float rep[4] = {0.f, 0.f, 0.f, 0.f};
    float att[4] = {0.f, 0.f, 0.f, 0.f};

    int per = (N + (int)gridDim.x - 1) / (int)gridDim.x;
    int s = blockIdx.x * per;
    int e = min(N, s + per);

    int i = s;
    for (; i + 1 < e; i += 2) {
        float4 h0 = __ldg(&g_hit[i]);
        float4 h1 = __ldg(&g_hit[i + 1]);
        int ti0 = __ldg(&tidx[i]);
        int ti1 = __ldg(&tidx[i + 1]);
        ull hx = pk2(h0.x, h1.x), hy = pk2(h0.y, h1.y), hw = pk2(h0.w, h1.w);
        float ua[8];
        #pragma unroll
        for (int j = 0; j < 4; j++) {
            ull u2 = fma2(mx2[j], hx, fma2(my2[j], hy, add2(hw, c22[j])));  // d2+1e-6, 2 hits
            float u0, u1; upk2(u0, u1, u2);
            float r0 = fmaxf(fmaf(-asqrtf(u0), h0.z, h0.z), 0.0f);   // max(q-q*sqrt,0); NaN->0
            float r1 = fmaxf(fmaf(-asqrtf(u1), h1.z, h1.z), 0.0f);
            rep[j] += r0;
            rep[j] += r1;
            ua[2 * j] = u0; ua[2 * j + 1] = u1;
        }
        if (ti0 >= 0 && (ti0 & 127) == t) {      // own-object pair (rare)
            int j = ti0 >> 7;
            #pragma unroll
            for (int j2 = 0; j2 < 4; j2++)
                if (j2 == j) {
                    float u = ua[2 * j2];
                    att[j2] = fmaf(u, h0.z, att[j2]);
                    rep[j2] -= fmaxf(fmaf(-asqrtf(u), h0.z, h0.z), 0.0f);
                }
        }
        if (ti1 >= 0 && (ti1 & 127) == t) {
            int j = ti1 >> 7;
            #pragma unroll
            for (int j2 = 0; j2 < 4; j2++)
                if (j2 == j) {
                    float u = ua[2 * j2 + 1];
                    att[j2] = fmaf(u, h1.z, att[j2]);
                    rep[j2] -= fmaxf(fmaf(-asqrtf(u), h1.z, h1.z), 0.0f);
                }
        }
    }
    if (i < e) {                                // odd remainder hit
        float4 h0 = __ldg(&g_hit[i]);
        int ti0 = __ldg(&tidx[i]);
        #pragma unroll
        for (int j = 0; j < 4; j++) {
            float mxl, mxh; upk2(mxl, mxh, mx2[j]); (void)mxh;
            float myl, myh; upk2(myl, myh, my2[j]); (void)myh;
            float cl,  ch;  upk2(cl,  ch,  c22[j]); (void)ch;
            float u = fmaf(mxl, h0.x, fmaf(myl, h0.y, h0.w)) + cl;
            float r = fmaxf(fmaf(-asqrtf(u), h0.z, h0.z), 0.0f);
            bool own = (ti0 == t + 128 * j);
            rep[j] += own ? 0.f : r;
            if (own) att[j] = fmaf(u, h0.z, att[j]);
        }
    }
    #pragma unroll
    for (int j = 0; j < 4; j++) {
        atomicAdd(&g_rep[t + 128 * j], rep[j]);
        atomicAdd(&g_att[t + 128 * j], att[j]);
    }

    // ---- last finishing block performs the final reduction + state reset ----
    __shared__ int s_last;
    __shared__ float sh[4][5];
    __threadfence();                             // release our atomics
    if (t == 0) s_last = (atomicAdd(&g_done, 1u) == (unsigned)gridDim.x - 1u) ? 1 : 0;
    __syncthreads();
    if (!s_last) return;
    __threadfence();                             // acquire all blocks' atomics

    float v0 = 0.f, v1 = 0.f, v2 = 0.f, v3 = 0.f, v4 = 0.f;
    #pragma unroll
    for (int j = 0; j < 4; j++) {
        int k = t + 128 * j;
        float c = g_cnt[k];
        if (c > 0.f) {
            unsigned long long key = g_key[k];
            unsigned a = 0xFFFFFFFFu - (unsigned)(key & 0xFFFFFFFFull);
            float qa = g_hit[a].z;
            float ba = __uint_as_float((unsigned)(key >> 32));
            v0 += qa * g_att[k] / (c + FEPS);
            v1 += qa * g_rep[k] / ((float)N - c + FEPS);
            v2 += 1.0f - ba;
            v3 += g_num[k] / (g_den[k] + FEPS);
            v4 += 1.f;
        }
        // reset for next graph replay
        g_cnt[k] = 0.f; g_key[k] = 0ull; g_num[k] = 0.f; g_den[k] = 0.f;
        g_att[k] = 0.f; g_rep[k] = 0.f;
    }
    int lane = t & 31, wid = t >> 5;
    #pragma unroll
    for (int o = 16; o; o >>= 1) {
        v0 += __shfl_down_sync(0xFFFFFFFFu, v0, o);
        v1 += __shfl_down_sync(0xFFFFFFFFu, v1, o);
        v2 += __shfl_down_sync(0xFFFFFFFFu, v2, o);
        v3 += __shfl_down_sync(0xFFFFFFFFu, v3, o);
        v4 += __shfl_down_sync(0xFFFFFFFFu, v4, o);
    }
    if (lane == 0) {
        sh[wid][0] = v0; sh[wid][1] = v1; sh[wid][2] = v2;
        sh[wid][3] = v3; sh[wid][4] = v4;
    }
    __syncthreads();
    if (t == 0) {
        float a0 = sh[0][0] + sh[1][0] + sh[2][0] + sh[3][0];
        float a1 = sh[0][1] + sh[1][1] + sh[2][1] + sh[3][1];
        float a2 = sh[0][2] + sh[1][2] + sh[2][2] + sh[3][2];
        float a3 = sh[0][3] + sh[1][3] + sh[2][3] + sh[3][3];
        float a4 = sh[0][4] + sh[1][4] + sh[2][4] + sh[3][4];
        float n_obj  = a4 + FEPS;
        float lnoise = g_scal[0] / (g_scal[1] + FEPS);
        float lcc    = 0.001f * g_scal[2] / (float)(2 * N);
        out[0] = (a0 + a1 + a2 + a3) / n_obj + lnoise + lcc;
        g_scal[0] = 0.f; g_scal[1] = 0.f; g_scal[2] = 0.f; g_scal[3] = 0.f;
        g_done = 0u;
    }
}

// ---------------- launch ----------------
extern "C" void kernel_launch(void* const* d_in, const int* in_sizes, int n_in,
                              void* d_out, int out_size) {
    const float* pbeta = (const float*)d_in[0];
    const float* pcc   = (const float*)d_in[1];
    const float* pen   = (const float*)d_in[2];
    const float* ppos  = (const float*)d_in[3];
    const float* ptime = (const float*)d_in[4];
    const float* pid   = (const float*)d_in[5];
    const int*   tidx  = (const int*)  d_in[6];
    const float* ten   = (const float*)d_in[7];
    const float* tpos  = (const float*)d_in[8];
    const float* ttime = (const float*)d_in[9];
    int N = in_sizes[0];
    if (N > MAXN) N = MAXN;

    passA_kernel<<<(N + 255) / 256, 256>>>(pbeta, pcc, pen, ppos, ptime, pid,
                                           tidx, ten, tpos, ttime, N);
    passC_kernel<<<CGRID, 128>>>(tidx, N, (float*)d_out);
}

// round 10
// speedup vs baseline: 1.3540x; 1.3540x over previous
#include <cuda_runtime.h>
#include <string.h>

#define MAXN 80000
#define KOBJ 512
#define FEPS 1e-9f
#define CGRID 1184   // 8 blocks/SM: proven single-wave, latency well hidden

// ---------------- scratch (static device globals; no allocation) ----------------
// Zero-initialized at load; passC's last block re-zeros accumulators each run.
__device__ __align__(16) float g_px[MAXN];     // hit x
__device__ __align__(16) float g_py[MAXN];     // hit y
__device__ __align__(16) float g_pw[MAXN];     // x^2+y^2+1e-6
__device__ __align__(16) float g_pq[MAXN];     // q
__device__ unsigned long long g_key[KOBJ];     // packed (beta_bits<<32) | ~index
__device__ float g_cnt[KOBJ], g_num[KOBJ], g_den[KOBJ];
__device__ float g_att[KOBJ], g_rep[KOBJ];
__device__ float g_scal[4];                    // noise_beta_sum, noise_cnt, cc_sum
__device__ unsigned int g_done;

// ---------------- helpers ----------------
typedef unsigned long long ull;
__device__ __forceinline__ float asqrtf(float x) {
    float r; asm("sqrt.approx.f32 %0, %1;" : "=f"(r) : "f"(x)); return r;
}
__device__ __forceinline__ float softclipf(float v, float s) {
    float x = v / s;
    if (x > 1.0f) x = __logf(x + 1.0f);
    return x * s;
}
__device__ __forceinline__ ull fma2(ull a, ull b, ull c) {
    ull d; asm("fma.rn.f32x2 %0, %1, %2, %3;" : "=l"(d) : "l"(a), "l"(b), "l"(c)); return d;
}
__device__ __forceinline__ ull add2(ull a, ull b) {
    ull d; asm("add.rn.f32x2 %0, %1, %2;" : "=l"(d) : "l"(a), "l"(b)); return d;
}
// register-pair reinterprets: compile to nothing (no asm movs!)
__device__ __forceinline__ float2 uf2(ull v) { float2 r; memcpy(&r, &v, 8); return r; }
__device__ __forceinline__ ull fu2(float2 v) { ull r; memcpy(&r, &v, 8); return r; }
__device__ __forceinline__ ull bc2(float v)  { return fu2(make_float2(v, v)); }

// ---------------- kernel 1: per-hit precompute + per-object atomics ----------------
__global__ void passA_kernel(const float* __restrict__ pbeta, const float* __restrict__ pcc,
                             const float* __restrict__ pen,   const float* __restrict__ ppos,
                             const float* __restrict__ ptime, const float* __restrict__ pid,
                             const int*   __restrict__ tidx,  const float* __restrict__ ten,
                             const float* __restrict__ tpos,  const float* __restrict__ ttime,
                             int N)
{
    int i = blockIdx.x * blockDim.x + threadIdx.x;
    float ccs = 0.f, nb = 0.f, nc = 0.f;
    if (i < N) {
        // hoisted, independent loads -> one batched round trip
        float  bref = pbeta[i];
        float2 cc   = ((const float2*)pcc)[i];
        float  pe   = pen[i];
        float2 pp   = ((const float2*)ppos)[i];
        float  pt   = ptime[i];
        int    k    = tidx[i];
        float  tev  = ten[i];
        float2 tp   = ((const float2*)tpos)[i];
        float  tt   = ttime[i];
        const float2* pid2 = (const float2*)pid;
        float2 c0 = pid2[3 * i], c1 = pid2[3 * i + 1], c2v = pid2[3 * i + 2];

        float b = fminf(fmaxf(bref, 1e-6f), 1.0f - 1e-6f);
        float a = 0.5f * __logf(__fdividef(1.0f + b, 1.0f - b));   // atanh
        float q = a * a + 0.1f;
        ccs = cc.x * cc.x + cc.y * cc.y;
        g_px[i] = cc.x; g_py[i] = cc.y; g_pq[i] = q; g_pw[i] = ccs + 1e-6f;

        float ed = fabsf(tev - pe);
        float el = softclipf(10.0f * __expf(-0.1f * ed * ed) + 0.01f * ed, 10.0f);
        float dx = tp.x - pp.x, dy = tp.y - pp.y;
        float d2 = dx * dx + dy * dy;
        float arg = asqrtf(d2 * 0.01f + 0.01f);
        float hub = (arg < 10.0f) ? arg * arg : 100.0f + 20.0f * (arg - 10.0f);
        float pl = softclipf(hub, 3.0f);
        float dt  = tt - pt;
        float adt = fabsf(dt);
        float th = (adt < 2.0f) ? dt * dt : 4.0f + 4.0f * (adt - 2.0f);
        float tl = softclipf(th, 6.0f);
        float cs = c0.x * c0.x + c0.y * c0.y + c1.x * c1.x + c1.y * c1.y
                 + c2v.x * c2v.x + c2v.y * c2v.y;
        float cl = 1e-8f * (cs * (1.0f / 6.0f));
        float payload = el + pl + tl + cl;
        float w  = (tev > 10.0f) ? 1.0f : fmaxf((tev - 0.5f) * (1.0f / 9.5f), 0.0f);
        float pw = b * w;

        if (k < 0) {
            nb = b; nc = 1.f;
        } else {
            atomicAdd(&g_cnt[k], 1.f);
            unsigned long long key =
                ((unsigned long long)__float_as_uint(b) << 32)
                | (unsigned long long)(0xFFFFFFFFu - (unsigned)i);
            atomicMax(&g_key[k], key);
            atomicAdd(&g_num[k], payload * pw);
            atomicAdd(&g_den[k], pw);
        }
    }
    #pragma unroll
    for (int o = 16; o; o >>= 1) {
        ccs += __shfl_down_sync(0xFFFFFFFFu, ccs, o);
        nb  += __shfl_down_sync(0xFFFFFFFFu, nb,  o);
        nc  += __shfl_down_sync(0xFFFFFFFFu, nc,  o);
    }
    if ((threadIdx.x & 31) == 0) {
        if (ccs != 0.f) atomicAdd(&g_scal[2], ccs);
        if (nc  != 0.f) { atomicAdd(&g_scal[0], nb); atomicAdd(&g_scal[1], nc); }
    }
}

// ---------------- kernel 2: N x K sweep (Q - S form) + inline finalization ----------------
__global__ void __launch_bounds__(128) passC_kernel(const int* __restrict__ tidx, int N,
                                                    float* __restrict__ out) {
    int t = threadIdx.x;                       // thread owns k = t, t+128, t+256, t+384
    ull mx2[4], my2[4], c22[4];
    #pragma unroll
    for (int j = 0; j < 4; j++) {
        int k = t + 128 * j;
        float mx = 0.f, my = 0.f, c2 = 0.f;
        unsigned long long key = __ldg(&g_key[k]);
        if (key != 0ull) {                     // nonzero iff object has members
            unsigned a = 0xFFFFFFFFu - (unsigned)(key & 0xFFFFFFFFull);
            float xa = __ldg(&g_px[a]), ya = __ldg(&g_py[a]);
            mx = -2.f * xa; my = -2.f * ya; c2 = xa * xa + ya * ya;
        }
        mx2[j] = bc2(mx); my2[j] = bc2(my); c22[j] = bc2(c2);
    }
    ull S2[4] = { 0ull, 0ull, 0ull, 0ull };    // packed sum of s*q per object
    ull Q2 = 0ull;                             // packed sum of q (shared by all objects)

    int per = 2 * ((N + 2 * CGRID - 1) / (2 * CGRID));   // even split -> aligned pair loads
    int s = blockIdx.x * per;
    int e = min(N, s + per);

    const ull*  px2 = (const ull*)g_px;
    const ull*  py2 = (const ull*)g_py;
    const ull*  pw2 = (const ull*)g_pw;
    const ull*  pq2 = (const ull*)g_pq;
    const int2* tx2 = (const int2*)tidx;

    int p = s >> 1, pe = e >> 1;
    for (; p < pe; ++p) {
        ull hx = __ldg(px2 + p), hy = __ldg(py2 + p);
        ull hw = __ldg(pw2 + p), hq = __ldg(pq2 + p);
        int2 ti = __ldg(tx2 + p);
        Q2 = add2(Q2, hq);
        ull u0, u1, u2, u3;
        {
            u0 = fma2(mx2[0], hx, fma2(my2[0], hy, add2(hw, c22[0])));
            u1 = fma2(mx2[1], hx, fma2(my2[1], hy, add2(hw, c22[1])));
            u2 = fma2(mx2[2], hx, fma2(my2[2], hy, add2(hw, c22[2])));
            u3 = fma2(mx2[3], hx, fma2(my2[3], hy, add2(hw, c22[3])));
            float2 a0 = uf2(u0), a1 = uf2(u1), a2 = uf2(u2), a3 = uf2(u3);
            float s00 = asqrtf(__saturatef(a0.x)), s01 = asqrtf(__saturatef(a0.y));
            float s10 = asqrtf(__saturatef(a1.x)), s11 = asqrtf(__saturatef(a1.y));
            float s20 = asqrtf(__saturatef(a2.x)), s21 = asqrtf(__saturatef(a2.y));
            float s30 = asqrtf(__saturatef(a3.x)), s31 = asqrtf(__saturatef(a3.y));
            S2[0] = fma2(fu2(make_float2(s00, s01)), hq, S2[0]);
            S2[1] = fma2(fu2(make_float2(s10, s11)), hq, S2[1]);
            S2[2] = fma2(fu2(make_float2(s20, s21)), hq, S2[2]);
            S2[3] = fma2(fu2(make_float2(s30, s31)), hq, S2[3]);
        }
        // own-object pairs: rare (78K of 41M) -> direct REDs, bit-identical recompute
        if (((unsigned)(ti.x - t) & 0xFFFFFE7Fu) == 0u) {
            int jj = (ti.x - t) >> 7;
            float hxs = uf2(hx).x, hys = uf2(hy).x, hws = uf2(hw).x, hqs = uf2(hq).x;
            #pragma unroll
            for (int j2 = 0; j2 < 4; j2++) if (j2 == jj) {
                float2 mxf = uf2(mx2[j2]), myf = uf2(my2[j2]), c2f = uf2(c22[j2]);
                float u  = fmaf(mxf.x, hxs, fmaf(myf.x, hys, hws + c2f.x));
                float ss = asqrtf(__saturatef(u));
                atomicAdd(&g_att[ti.x], u * hqs);
                atomicAdd(&g_rep[ti.x], fmaf(ss, hqs, -hqs));   // remove own (q - s*q)
            }
        }
        if (((unsigned)(ti.y - t) & 0xFFFFFE7Fu) == 0u) {
            int jj = (ti.y - t) >> 7;
            float hxs = uf2(hx).y, hys = uf2(hy).y, hws = uf2(hw).y, hqs = uf2(hq).y;
            #pragma unroll
            for (int j2 = 0; j2 < 4; j2++) if (j2 == jj) {
                float2 mxf = uf2(mx2[j2]), myf = uf2(my2[j2]), c2f = uf2(c22[j2]);
                float u  = fmaf(mxf.x, hxs, fmaf(myf.x, hys, hws + c2f.x));
                float ss = asqrtf(__saturatef(u));
                atomicAdd(&g_att[ti.y], u * hqs);
                atomicAdd(&g_rep[ti.y], fmaf(ss, hqs, -hqs));
            }
        }
    }

    // odd-N tail (never taken for N=80000, kept for generality)
    float Qx = 0.f, Sx[4] = {0.f, 0.f, 0.f, 0.f};
    if ((e & 1) && s < e) {
        int i = e - 1;
        float hxs = g_px[i], hys = g_py[i], hws = g_pw[i], hqs = g_pq[i];
        int ti = tidx[i];
        Qx = hqs;
        #pragma unroll
        for (int j = 0; j < 4; j++) {
            float2 mxf = uf2(mx2[j]), myf = uf2(my2[j]), c2f = uf2(c22[j]);
            float u  = fmaf(mxf.x, hxs, fmaf(myf.x, hys, hws + c2f.x));
            float ss = asqrtf(__saturatef(u));
            Sx[j] = ss * hqs;
            if (ti == t + 128 * j) {
                atomicAdd(&g_att[ti], u * hqs);
                atomicAdd(&g_rep[ti], fmaf(ss, hqs, -hqs));
            }
        }
    }

    float2 Qf = uf2(Q2);
    float Qt = Qf.x + Qf.y + Qx;
    #pragma unroll
    for (int j = 0; j < 4; j++) {
        float2 Sf = uf2(S2[j]);
        atomicAdd(&g_rep[t + 128 * j], Qt - Sf.x - Sf.y - Sx[j]);
    }

    // ---- last finishing block: final reduction + state reset ----
    __shared__ int s_last;
    __shared__ float sh[4][5];
    __threadfence();
    if (t == 0) s_last = (atomicAdd(&g_done, 1u) == (unsigned)gridDim.x - 1u) ? 1 : 0;
    __syncthreads();
    if (!s_last) return;
    __threadfence();

    float v0 = 0.f, v1 = 0.f, v2 = 0.f, v3 = 0.f, v4 = 0.f;
    #pragma unroll
    for (int j = 0; j < 4; j++) {
        int k = t + 128 * j;
        float c = g_cnt[k];
        if (c > 0.f) {
            unsigned long long key = g_key[k];
            unsigned a = 0xFFFFFFFFu - (unsigned)(key & 0xFFFFFFFFull);
            float qa = g_pq[a];
            float ba = __uint_as_float((unsigned)(key >> 32));
            v0 += qa * g_att[k] / (c + FEPS);
            v1 += qa * g_rep[k] / ((float)N - c + FEPS);
            v2 += 1.0f - ba;
            v3 += g_num[k] / (g_den[k] + FEPS);
            v4 += 1.f;
        }
        g_cnt[k] = 0.f; g_key[k] = 0ull; g_num[k] = 0.f; g_den[k] = 0.f;
        g_att[k] = 0.f; g_rep[k] = 0.f;
    }
    int lane = t & 31, wid = t >> 5;
    #pragma unroll
    for (int o = 16; o; o >>= 1) {
        v0 += __shfl_down_sync(0xFFFFFFFFu, v0, o);
        v1 += __shfl_down_sync(0xFFFFFFFFu, v1, o);
        v2 += __shfl_down_sync(0xFFFFFFFFu, v2, o);
        v3 += __shfl_down_sync(0xFFFFFFFFu, v3, o);
        v4 += __shfl_down_sync(0xFFFFFFFFu, v4, o);
    }
    if (lane == 0) {
        sh[wid][0] = v0; sh[wid][1] = v1; sh[wid][2] = v2;
        sh[wid][3] = v3; sh[wid][4] = v4;
    }
    __syncthreads();
    if (t == 0) {
        float a0 = sh[0][0] + sh[1][0] + sh[2][0] + sh[3][0];
        float a1 = sh[0][1] + sh[1][1] + sh[2][1] + sh[3][1];
        float a2 = sh[0][2] + sh[1][2] + sh[2][2] + sh[3][2];
        float a3 = sh[0][3] + sh[1][3] + sh[2][3] + sh[3][3];
        float a4 = sh[0][4] + sh[1][4] + sh[2][4] + sh[3][4];
        float n_obj  = a4 + FEPS;
        float lnoise = g_scal[0] / (g_scal[1] + FEPS);
        float lcc    = 0.001f * g_scal[2] / (float)(2 * N);
        out[0] = (a0 + a1 + a2 + a3) / n_obj + lnoise + lcc;
        g_scal[0] = 0.f; g_scal[1] = 0.f; g_scal[2] = 0.f; g_scal[3] = 0.f;
        g_done = 0u;
    }
}

// ---------------- launch ----------------
extern "C" void kernel_launch(void* const* d_in, const int* in_sizes, int n_in,
                              void* d_out, int out_size) {
    const float* pbeta = (const float*)d_in[0];
    const float* pcc   = (const float*)d_in[1];
    const float* pen   = (const float*)d_in[2];
    const float* ppos  = (const float*)d_in[3];
    const float* ptime = (const float*)d_in[4];
    const float* pid   = (const float*)d_in[5];
    const int*   tidx  = (const int*)  d_in[6];
    const float* ten   = (const float*)d_in[7];
    const float* tpos  = (const float*)d_in[8];
    const float* ttime = (const float*)d_in[9];
    int N = in_sizes[0];
    if (N > MAXN) N = MAXN;

    passA_kernel<<<(N + 255) / 256, 256>>>(pbeta, pcc, pen, ppos, ptime, pid,
                                           tidx, ten, tpos, ttime, N);
    passC_kernel<<<CGRID, 128>>>(tidx, N, (float*)d_out);
}